// round 5
// baseline (speedup 1.0000x reference)
#include <cuda_runtime.h>
#include <stdint.h>
#include <stddef.h>

#define B_ 4
#define S_ 2048
#define HID_ 768
#define H_ 12
#define D_ 64
#define BH_ 48
#define MROWS 8192
#define OUTE 6291456
#define SCALE_ 0.125f
#define FLTMAX_ 3.402823466e38f

// Scratch: q, k, v (BHSD each) + context (row-major [8192,768])
__device__ float g_scratch[4ull * 6291456ull];
// Bitmask: [B][S][S/32]
__device__ uint32_t g_bm[524288];

// ---------------------------------------------------------------------------
__device__ __forceinline__ uint32_t f2t(float f) {
    uint32_t r;
    asm("cvt.rna.tf32.f32 %0, %1;" : "=r"(r) : "f"(f));
    return r;
}
__device__ __forceinline__ uint2 pf2(float a, float b) {
    return make_uint2(f2t(a), f2t(b));
}

__device__ __forceinline__ void mma8(float* c,
    uint32_t a0, uint32_t a1, uint32_t a2, uint32_t a3,
    uint32_t b0, uint32_t b1)
{
    asm volatile(
        "mma.sync.aligned.m16n8k8.row.col.f32.tf32.tf32.f32 "
        "{%0,%1,%2,%3}, {%4,%5,%6,%7}, {%8,%9}, {%0,%1,%2,%3};"
        : "+f"(c[0]), "+f"(c[1]), "+f"(c[2]), "+f"(c[3])
        : "r"(a0), "r"(a1), "r"(a2), "r"(a3), "r"(b0), "r"(b1));
}

// ---------------------------------------------------------------------------
// Bitmask builder: mask int32 -> bits (1 = masked)
// ---------------------------------------------------------------------------
__global__ __launch_bounds__(256) void build_bitmask(
    const int* __restrict__ mask, uint32_t* __restrict__ bm)
{
    int idx = blockIdx.x * 256 + threadIdx.x;
    const int* p = mask + (size_t)idx * 32;
    uint32_t r = 0;
#pragma unroll
    for (int j = 0; j < 8; j++) {
        int4 v = *(const int4*)(p + 4 * j);
        r |= (v.x != 0 ? 1u : 0u) << (4 * j);
        r |= (v.y != 0 ? 1u : 0u) << (4 * j + 1);
        r |= (v.z != 0 ? 1u : 0u) << (4 * j + 2);
        r |= (v.w != 0 ? 1u : 0u) << (4 * j + 3);
    }
    bm[idx] = r;
}

// ---------------------------------------------------------------------------
// Shared GEMM core with k-pair smem layouts.
// Xs2: [128 rows][20 pairs]  pair = (k, k+4), kk8 groups of 4
// Ws2: [16 pair-rows][132 cols]
// ---------------------------------------------------------------------------
struct GemmSmem {
    uint2 Xs2[128 * 20];
    uint2 Ws2[16 * 132];
};

template <int MODE>
__device__ __forceinline__ void gemm_core(
    const float* __restrict__ X, const float* __restrict__ W,
    const float* __restrict__ bias, float* __restrict__ out,
    GemmSmem& sm, int m0, int n0)
{
    const int tid  = threadIdx.x;
    const int w    = tid >> 5;
    const int lane = tid & 31;
    const int g    = lane >> 2;
    const int t    = lane & 3;
    const int wm   = (w & 1) * 64;
    const int wn   = (w >> 1) * 32;

    float acc[4][4][4];
#pragma unroll
    for (int mi = 0; mi < 4; mi++)
#pragma unroll
        for (int ni = 0; ni < 4; ni++)
#pragma unroll
            for (int r = 0; r < 4; r++) acc[mi][ni][r] = 0.f;

    for (int k0 = 0; k0 < HID_; k0 += 32) {
        // X tile 128x32 -> pairs
        {
            int r = tid >> 1, j = tid & 1;      // j: 16-k group
            const float* src = X + (size_t)(m0 + r) * HID_ + k0 + 16 * j;
            float4 va = *(const float4*)(src);
            float4 vb = *(const float4*)(src + 4);
            float4 vc = *(const float4*)(src + 8);
            float4 vd = *(const float4*)(src + 12);
            uint2* dst = &sm.Xs2[r * 20 + 8 * j];
            dst[0] = pf2(va.x, vb.x); dst[1] = pf2(va.y, vb.y);
            dst[2] = pf2(va.z, vb.z); dst[3] = pf2(va.w, vb.w);
            dst[4] = pf2(vc.x, vd.x); dst[5] = pf2(vc.y, vd.y);
            dst[6] = pf2(vc.z, vd.z); dst[7] = pf2(vc.w, vd.w);
        }
        // W tile 32x128 -> pair-rows
#pragma unroll
        for (int i = 0; i < 2; i++) {
            int u = tid + 256 * i;              // 0..511
            int pr = u >> 5;                    // 0..15
            int c4 = u & 31;                    // 0..31
            int kk8 = pr >> 2, tt = pr & 3;
            int row = 8 * kk8 + tt;
            const float* lo = W + (size_t)(k0 + row) * HID_ + n0 + 4 * c4;
            const float* hi = lo + 4 * HID_;
            float4 vl = *(const float4*)lo;
            float4 vh = *(const float4*)hi;
            uint2* dst = &sm.Ws2[pr * 132 + 4 * c4];
            dst[0] = pf2(vl.x, vh.x); dst[1] = pf2(vl.y, vh.y);
            dst[2] = pf2(vl.z, vh.z); dst[3] = pf2(vl.w, vh.w);
        }
        __syncthreads();

#pragma unroll
        for (int kk8 = 0; kk8 < 4; kk8++) {
            uint2 a[4][2];
            uint2 b[4];
#pragma unroll
            for (int mi = 0; mi < 4; mi++) {
                int mr = wm + 16 * mi + g;
                a[mi][0] = sm.Xs2[mr * 20 + kk8 * 4 + t];
                a[mi][1] = sm.Xs2[(mr + 8) * 20 + kk8 * 4 + t];
            }
#pragma unroll
            for (int ni = 0; ni < 4; ni++)
                b[ni] = sm.Ws2[(kk8 * 4 + t) * 132 + wn + 8 * ni + g];
#pragma unroll
            for (int mi = 0; mi < 4; mi++)
#pragma unroll
                for (int ni = 0; ni < 4; ni++)
                    mma8(acc[mi][ni], a[mi][0].x, a[mi][1].x,
                         a[mi][0].y, a[mi][1].y, b[ni].x, b[ni].y);
        }
        __syncthreads();
    }

#pragma unroll
    for (int mi = 0; mi < 4; mi++) {
        int r0 = m0 + wm + 16 * mi + g;
        int r1 = r0 + 8;
#pragma unroll
        for (int ni = 0; ni < 4; ni++) {
            int col = n0 + wn + 8 * ni + 2 * t;
            float bb0 = bias[col], bb1 = bias[col + 1];
            float2 v0 = make_float2(acc[mi][ni][0] + bb0, acc[mi][ni][1] + bb1);
            float2 v1 = make_float2(acc[mi][ni][2] + bb0, acc[mi][ni][3] + bb1);
            if (MODE == 0) {
                int h = col >> 6, d = col & 63;
                int b0r = r0 >> 11, s0 = r0 & 2047;
                int b1r = r1 >> 11, s1 = r1 & 2047;
                *(float2*)&out[(((size_t)(b0r * H_ + h) * S_ + s0) << 6) + d] = v0;
                *(float2*)&out[(((size_t)(b1r * H_ + h) * S_ + s1) << 6) + d] = v1;
            } else {
                *(float2*)&out[(size_t)r0 * HID_ + col] = v0;
                *(float2*)&out[(size_t)r1 * HID_ + col] = v1;
            }
        }
    }
}

__global__ __launch_bounds__(256, 2) void gemm_qkv(
    const float* __restrict__ Xq, const float* __restrict__ Xk, const float* __restrict__ Xv,
    const float* __restrict__ Wq, const float* __restrict__ Wk, const float* __restrict__ Wv,
    const float* __restrict__ bq, const float* __restrict__ bk, const float* __restrict__ bv,
    float* __restrict__ oq, float* __restrict__ ok, float* __restrict__ ov)
{
    __shared__ GemmSmem sm;
    const int z = blockIdx.z;
    const float* X    = (z == 0) ? Xq : (z == 1) ? Xk : Xv;
    const float* W    = (z == 0) ? Wq : (z == 1) ? Wk : Wv;
    const float* bias = (z == 0) ? bq : (z == 1) ? bk : bv;
    float* out        = (z == 0) ? oq : (z == 1) ? ok : ov;
    gemm_core<0>(X, W, bias, out, sm, blockIdx.y * 128, blockIdx.x * 128);
}

__global__ __launch_bounds__(256, 2) void gemm_out(
    const float* __restrict__ X, const float* __restrict__ W,
    const float* __restrict__ bias, float* __restrict__ out)
{
    __shared__ GemmSmem sm;
    gemm_core<1>(X, W, bias, out, sm, blockIdx.y * 128, blockIdx.x * 128);
}

// ---------------------------------------------------------------------------
// Fused attention with pair layouts.
// Qs2: [128][36 pairs]   (8B)  pair=(k,k+4)
// Ks2: [64][36 pairs]
// Vs2: [32 pair-rows][68 cols] pair=(row k, row k+4)
// Ps : [128][72] 32-bit, plain layout
// ---------------------------------------------------------------------------
#define QS2_WORDS (2 * 128 * 36)
#define KS2_WORDS (2 * 64 * 36)
#define VS2_WORDS (2 * 32 * 68)
#define PS_PITCH  72
#define FUSED_SMEM ((QS2_WORDS + KS2_WORDS + VS2_WORDS + 128 * PS_PITCH) * 4)

__global__ __launch_bounds__(256, 2) void fused_attn(
    const float* __restrict__ qg, const float* __restrict__ kg,
    const float* __restrict__ vg, const uint32_t* __restrict__ bm,
    float* __restrict__ probs, float* __restrict__ ctx)
{
    extern __shared__ uint32_t sh[];
    uint2* Qs2 = (uint2*)sh;
    uint2* Ks2 = (uint2*)(sh + QS2_WORDS);
    uint2* Vs2 = (uint2*)(sh + QS2_WORDS + KS2_WORDS);
    uint32_t* Ps = sh + QS2_WORDS + KS2_WORDS + VS2_WORDS;

    const int tid  = threadIdx.x;
    const int w    = tid >> 5;
    const int lane = tid & 31;
    const int g    = lane >> 2;
    const int t    = lane & 3;
    const int wr   = w * 16;
    const int q0   = blockIdx.x * 128;
    const int bh   = blockIdx.y;
    const int bb   = bh / H_;
    const int h    = bh % H_;
    const float* qbase = qg + (size_t)bh * S_ * D_;
    const float* kbase = kg + (size_t)bh * S_ * D_;
    const float* vbase = vg + (size_t)bh * S_ * D_;

    const int r0 = q0 + wr + g;
    const int r1 = r0 + 8;
    const uint32_t* bm0 = bm + ((size_t)bb * S_ + r0) * 64;
    const uint32_t* bm1 = bm + ((size_t)bb * S_ + r1) * 64;

    // Load Q tile 128x64 into pair layout. 512 units (row, 16k-group).
#pragma unroll
    for (int i = 0; i < 2; i++) {
        int u = tid + 256 * i;
        int r = u >> 2, j = u & 3;
        const float* src = qbase + (size_t)(q0 + r) * D_ + 16 * j;
        float4 va = *(const float4*)(src);
        float4 vb = *(const float4*)(src + 4);
        float4 vc = *(const float4*)(src + 8);
        float4 vd = *(const float4*)(src + 12);
        uint2* dst = &Qs2[r * 36 + 8 * j];
        dst[0] = pf2(va.x, vb.x); dst[1] = pf2(va.y, vb.y);
        dst[2] = pf2(va.z, vb.z); dst[3] = pf2(va.w, vb.w);
        dst[4] = pf2(vc.x, vd.x); dst[5] = pf2(vc.y, vd.y);
        dst[6] = pf2(vc.z, vd.z); dst[7] = pf2(vc.w, vd.w);
    }
    __syncthreads();

    float m0v = -FLTMAX_, m1v = -FLTMAX_;
    float s0v = 0.f, s1v = 0.f;

    // ---------------- Pass 1: stats ----------------
    for (int k0 = 0; k0 < S_; k0 += 64) {
        // K tile 64x64 -> pairs: 256 units
        {
            int r = tid >> 2, j = tid & 3;
            const float* src = kbase + (size_t)(k0 + r) * D_ + 16 * j;
            float4 va = *(const float4*)(src);
            float4 vb = *(const float4*)(src + 4);
            float4 vc = *(const float4*)(src + 8);
            float4 vd = *(const float4*)(src + 12);
            uint2* dst = &Ks2[r * 36 + 8 * j];
            dst[0] = pf2(va.x, vb.x); dst[1] = pf2(va.y, vb.y);
            dst[2] = pf2(va.z, vb.z); dst[3] = pf2(va.w, vb.w);
            dst[4] = pf2(vc.x, vd.x); dst[5] = pf2(vc.y, vd.y);
            dst[6] = pf2(vc.z, vd.z); dst[7] = pf2(vc.w, vd.w);
        }
        __syncthreads();

        float acc[8][4];
#pragma unroll
        for (int ni = 0; ni < 8; ni++)
#pragma unroll
            for (int r = 0; r < 4; r++) acc[ni][r] = 0.f;

#pragma unroll
        for (int kk8 = 0; kk8 < 8; kk8++) {
            uint2 pa0 = Qs2[(wr + g) * 36 + kk8 * 4 + t];
            uint2 pa1 = Qs2[(wr + g + 8) * 36 + kk8 * 4 + t];
#pragma unroll
            for (int ni = 0; ni < 8; ni++) {
                uint2 pb = Ks2[(8 * ni + g) * 36 + kk8 * 4 + t];
                mma8(acc[ni], pa0.x, pa1.x, pa0.y, pa1.y, pb.x, pb.y);
            }
        }

        uint2 w0 = *(const uint2*)(bm0 + (k0 >> 5));
        uint2 w1 = *(const uint2*)(bm1 + (k0 >> 5));
        float lm0 = -FLTMAX_, lm1 = -FLTMAX_;
#pragma unroll
        for (int ni = 0; ni < 8; ni++) {
            uint32_t sel0 = (ni < 4) ? w0.x : w0.y;
            uint32_t sel1 = (ni < 4) ? w1.x : w1.y;
            int bit = (8 * ni + 2 * t) & 31;
            acc[ni][0] = ((sel0 >> bit) & 1)       ? -1e9f : acc[ni][0] * SCALE_;
            acc[ni][1] = ((sel0 >> (bit + 1)) & 1) ? -1e9f : acc[ni][1] * SCALE_;
            acc[ni][2] = ((sel1 >> bit) & 1)       ? -1e9f : acc[ni][2] * SCALE_;
            acc[ni][3] = ((sel1 >> (bit + 1)) & 1) ? -1e9f : acc[ni][3] * SCALE_;
            lm0 = fmaxf(lm0, fmaxf(acc[ni][0], acc[ni][1]));
            lm1 = fmaxf(lm1, fmaxf(acc[ni][2], acc[ni][3]));
        }
        lm0 = fmaxf(lm0, __shfl_xor_sync(0xffffffffu, lm0, 1));
        lm0 = fmaxf(lm0, __shfl_xor_sync(0xffffffffu, lm0, 2));
        lm1 = fmaxf(lm1, __shfl_xor_sync(0xffffffffu, lm1, 1));
        lm1 = fmaxf(lm1, __shfl_xor_sync(0xffffffffu, lm1, 2));

        float mn0 = fmaxf(m0v, lm0);
        float mn1 = fmaxf(m1v, lm1);
        float sc0 = __expf(m0v - mn0);
        float sc1 = __expf(m1v - mn1);
        float ls0 = 0.f, ls1 = 0.f;
#pragma unroll
        for (int ni = 0; ni < 8; ni++) {
            ls0 += __expf(acc[ni][0] - mn0) + __expf(acc[ni][1] - mn0);
            ls1 += __expf(acc[ni][2] - mn1) + __expf(acc[ni][3] - mn1);
        }
        s0v = s0v * sc0 + ls0;
        s1v = s1v * sc1 + ls1;
        m0v = mn0; m1v = mn1;
        __syncthreads();
    }

    float S0 = s0v + __shfl_xor_sync(0xffffffffu, s0v, 1);
    S0 += __shfl_xor_sync(0xffffffffu, S0, 2);
    float S1 = s1v + __shfl_xor_sync(0xffffffffu, s1v, 1);
    S1 += __shfl_xor_sync(0xffffffffu, S1, 2);
    float inv0 = 1.f / S0;
    float inv1 = 1.f / S1;

    float accv[8][4];
#pragma unroll
    for (int ni = 0; ni < 8; ni++)
#pragma unroll
        for (int r = 0; r < 4; r++) accv[ni][r] = 0.f;

    float* pr0 = probs + ((size_t)bh * S_ + r0) * S_;
    float* pr1 = probs + ((size_t)bh * S_ + r1) * S_;

    // ---------------- Pass 2: probs + PV ----------------
    for (int k0 = 0; k0 < S_; k0 += 64) {
        // K tile
        {
            int r = tid >> 2, j = tid & 3;
            const float* src = kbase + (size_t)(k0 + r) * D_ + 16 * j;
            float4 va = *(const float4*)(src);
            float4 vb = *(const float4*)(src + 4);
            float4 vc = *(const float4*)(src + 8);
            float4 vd = *(const float4*)(src + 12);
            uint2* dst = &Ks2[r * 36 + 8 * j];
            dst[0] = pf2(va.x, vb.x); dst[1] = pf2(va.y, vb.y);
            dst[2] = pf2(va.z, vb.z); dst[3] = pf2(va.w, vb.w);
            dst[4] = pf2(vc.x, vd.x); dst[5] = pf2(vc.y, vd.y);
            dst[6] = pf2(vc.z, vd.z); dst[7] = pf2(vc.w, vd.w);
        }
        // V tile 64x64 -> pair-rows: 512 units
#pragma unroll
        for (int i = 0; i < 2; i++) {
            int u = tid + 256 * i;
            int pr = u >> 4;            // 0..31
            int c4 = u & 15;            // 0..15
            int kk8 = pr >> 2, tt = pr & 3;
            int krow = 8 * kk8 + tt;
            const float* lo = vbase + (size_t)(k0 + krow) * D_ + 4 * c4;
            const float* hi = lo + 4 * D_;
            float4 vl = *(const float4*)lo;
            float4 vh = *(const float4*)hi;
            uint2* dst = &Vs2[pr * 68 + 4 * c4];
            dst[0] = pf2(vl.x, vh.x); dst[1] = pf2(vl.y, vh.y);
            dst[2] = pf2(vl.z, vh.z); dst[3] = pf2(vl.w, vh.w);
        }
        __syncthreads();

        float acc[8][4];
#pragma unroll
        for (int ni = 0; ni < 8; ni++)
#pragma unroll
            for (int r = 0; r < 4; r++) acc[ni][r] = 0.f;

#pragma unroll
        for (int kk8 = 0; kk8 < 8; kk8++) {
            uint2 pa0 = Qs2[(wr + g) * 36 + kk8 * 4 + t];
            uint2 pa1 = Qs2[(wr + g + 8) * 36 + kk8 * 4 + t];
#pragma unroll
            for (int ni = 0; ni < 8; ni++) {
                uint2 pb = Ks2[(8 * ni + g) * 36 + kk8 * 4 + t];
                mma8(acc[ni], pa0.x, pa1.x, pa0.y, pa1.y, pb.x, pb.y);
            }
        }

        uint2 w0 = *(const uint2*)(bm0 + (k0 >> 5));
        uint2 w1 = *(const uint2*)(bm1 + (k0 >> 5));
#pragma unroll
        for (int ni = 0; ni < 8; ni++) {
            uint32_t sel0 = (ni < 4) ? w0.x : w0.y;
            uint32_t sel1 = (ni < 4) ? w1.x : w1.y;
            int bit = (8 * ni + 2 * t) & 31;
            float v00 = ((sel0 >> bit) & 1)       ? -1e9f : acc[ni][0] * SCALE_;
            float v01 = ((sel0 >> (bit + 1)) & 1) ? -1e9f : acc[ni][1] * SCALE_;
            float v10 = ((sel1 >> bit) & 1)       ? -1e9f : acc[ni][2] * SCALE_;
            float v11 = ((sel1 >> (bit + 1)) & 1) ? -1e9f : acc[ni][3] * SCALE_;
            float p00 = __expf(v00 - m0v) * inv0;
            float p01 = __expf(v01 - m0v) * inv0;
            float p10 = __expf(v10 - m1v) * inv1;
            float p11 = __expf(v11 - m1v) * inv1;
            int c = k0 + 8 * ni + 2 * t;
            *(float2*)(pr0 + c) = make_float2(p00, p01);
            *(float2*)(pr1 + c) = make_float2(p10, p11);
            int cl = 8 * ni + 2 * t;
            *(uint2*)&Ps[(wr + g) * PS_PITCH + cl]     = make_uint2(f2t(p00), f2t(p01));
            *(uint2*)&Ps[(wr + g + 8) * PS_PITCH + cl] = make_uint2(f2t(p10), f2t(p11));
        }
        __syncwarp();

#pragma unroll
        for (int kk = 0; kk < 64; kk += 8) {
            uint32_t a0 = Ps[(wr + g) * PS_PITCH + kk + t];
            uint32_t a1 = Ps[(wr + g + 8) * PS_PITCH + kk + t];
            uint32_t a2 = Ps[(wr + g) * PS_PITCH + kk + t + 4];
            uint32_t a3 = Ps[(wr + g + 8) * PS_PITCH + kk + t + 4];
            int kk8 = kk >> 3;
#pragma unroll
            for (int ni = 0; ni < 8; ni++) {
                uint2 pb = Vs2[(kk8 * 4 + t) * 68 + 8 * ni + g];
                mma8(accv[ni], a0, a1, a2, a3, pb.x, pb.y);
            }
        }
        __syncthreads();
    }

#pragma unroll
    for (int ni = 0; ni < 8; ni++) {
        int col = h * D_ + 8 * ni + 2 * t;
        *(float2*)&ctx[((size_t)(bb * S_ + r0)) * HID_ + col] =
            make_float2(accv[ni][0], accv[ni][1]);
        *(float2*)&ctx[((size_t)(bb * S_ + r1)) * HID_ + col] =
            make_float2(accv[ni][2], accv[ni][3]);
    }
}

// ---------------------------------------------------------------------------
extern "C" void kernel_launch(void* const* d_in, const int* in_sizes, int n_in,
                              void* d_out, int out_size)
{
    (void)in_sizes; (void)n_in; (void)out_size;
    const float* Q  = (const float*)d_in[0];
    const float* K  = (const float*)d_in[1];
    const float* V  = (const float*)d_in[2];
    const int*   mask = (const int*)d_in[3];
    const float* Wq = (const float*)d_in[4];
    const float* bq = (const float*)d_in[5];
    const float* Wk = (const float*)d_in[6];
    const float* bk = (const float*)d_in[7];
    const float* Wv = (const float*)d_in[8];
    const float* bv = (const float*)d_in[9];
    const float* Wo = (const float*)d_in[10];
    const float* bo = (const float*)d_in[11];

    float* out   = (float*)d_out;
    float* probs = out + OUTE;

    float* scratch = nullptr;
    cudaGetSymbolAddress((void**)&scratch, g_scratch);
    uint32_t* bmp = nullptr;
    cudaGetSymbolAddress((void**)&bmp, g_bm);
    float* gq   = scratch;
    float* gk   = scratch + (size_t)OUTE;
    float* gv   = scratch + 2ull * OUTE;
    float* gctx = scratch + 3ull * OUTE;

    cudaFuncSetAttribute(fused_attn, cudaFuncAttributeMaxDynamicSharedMemorySize,
                         FUSED_SMEM);

    build_bitmask<<<2048, 256>>>(mask, bmp);
    gemm_qkv<<<dim3(HID_ / 128, MROWS / 128, 3), 256>>>(
        Q, K, V, Wq, Wk, Wv, bq, bk, bv, gq, gk, gv);
    fused_attn<<<dim3(S_ / 128, BH_), 256, FUSED_SMEM>>>(gq, gk, gv, bmp, probs, gctx);
    gemm_out<<<dim3(HID_ / 128, MROWS / 128), 256>>>(gctx, Wo, bo, out);
}